// round 9
// baseline (speedup 1.0000x reference)
#include <cuda_runtime.h>
#include <cuda_bf16.h>
#include <math.h>

// Problem constants
#define BB   256                 // batch
#define TT   2048                // seq len
#define VV   128                 // vocab / input size
#define HH   64                  // hidden
#define GG   256                 // 4 gates * HH
#define MM   (BB * TT)           // 524288 rows

// Scratch (device-global; no runtime allocation allowed)
__device__ float g_Wx[VV * GG];            // fused x-part weights [128,256]
__device__ float g_Wh[HH * GG];            // fused h-part weights [64,256]
__device__ float g_bias[GG];               // fused gate biases
__device__ float g_preact[(size_t)MM * GG];  // 512 MB: x-part preactivations
__device__ float g_H[(size_t)MM * HH];       // 128 MB: hidden states per step

__device__ __forceinline__ unsigned int to_tf32(float v) {
    unsigned int r;
    asm("cvt.rna.tf32.f32 %0, %1;" : "=r"(r) : "f"(v));
    return r;
}
__device__ __forceinline__ float tanh_fast(float x) {
    float y;
    asm("tanh.approx.f32 %0, %1;" : "=f"(y) : "f"(x));
    return y;
}
// sigmoid(v) = 0.5*tanh(0.5*v) + 0.5
__device__ __forceinline__ float sig05(float v) {
    return fmaf(tanh_fast(0.5f * v), 0.5f, 0.5f);
}

// ---------------------------------------------------------------------------
// Kernel 0: pack 4 gate weight matrices into fused layouts.
// Gate order: 0..63 = f, 64..127 = if, 128..191 = ic(tanh), 192..255 = o
// ---------------------------------------------------------------------------
__global__ void pack_weights(const float* __restrict__ Wf,  const float* __restrict__ bf,
                             const float* __restrict__ Wif, const float* __restrict__ bif,
                             const float* __restrict__ Wic, const float* __restrict__ bic,
                             const float* __restrict__ Wo,  const float* __restrict__ bo) {
    int g = blockIdx.x * blockDim.x + threadIdx.x;
    if (g >= GG) return;
    int gate = g >> 6;
    int col  = g & 63;
    const float* W = (gate == 0) ? Wf : (gate == 1) ? Wif : (gate == 2) ? Wic : Wo;
    const float* bv = (gate == 0) ? bf : (gate == 1) ? bif : (gate == 2) ? bic : bo;
    g_bias[g] = bv[col];
    for (int k = 0; k < VV; k++)
        g_Wx[k * GG + g] = W[k * HH + col];
    for (int j = 0; j < HH; j++)
        g_Wh[j * GG + g] = W[(VV + j) * HH + col];
}

// ---------------------------------------------------------------------------
// Kernel 1: preact[m, g] = x[m, :] @ Wx[:, g] + bias[g]   via TF32 mma.sync
// ---------------------------------------------------------------------------
#define AS_STRIDE 132
#define BS_STRIDE 72

__global__ __launch_bounds__(256) void gemm_x(const float* __restrict__ x) {
    extern __shared__ unsigned int smem[];
    unsigned int* As = smem;                       // 128 * 132 words
    unsigned int* Bs = smem + 128 * AS_STRIDE;     // 128 * 72 words

    const int m0 = blockIdx.x * 128;
    const int tid  = threadIdx.x;
    const int lane = tid & 31;
    const int warp = tid >> 5;
    const int wm = warp >> 1;      // 0..3  (M)
    const int wn = warp & 1;       // 0..1  (N)
    const int gp = lane >> 2;      // 0..7
    const int tq = lane & 3;       // 0..3

    #pragma unroll
    for (int i = 0; i < 16; i++) {
        int t  = tid + i * 256;            // float4 index 0..4095
        int r  = t >> 5;
        int c4 = (t & 31) * 4;
        float4 v = *reinterpret_cast<const float4*>(&x[(size_t)(m0 + r) * VV + c4]);
        unsigned int* dst = &As[r * AS_STRIDE + c4];
        dst[0] = to_tf32(v.x); dst[1] = to_tf32(v.y);
        dst[2] = to_tf32(v.z); dst[3] = to_tf32(v.w);
    }

    for (int nb = 0; nb < 4; nb++) {
        const int n0 = nb * 64;
        __syncthreads();

        #pragma unroll
        for (int i = 0; i < 8; i++) {
            int t  = tid + i * 256;            // float4 index 0..2047
            int k  = t >> 4;
            int c4 = (t & 15) * 4;
            float4 v = *reinterpret_cast<const float4*>(&g_Wx[(size_t)k * GG + n0 + c4]);
            unsigned int* dst = &Bs[k * BS_STRIDE + c4];
            dst[0] = to_tf32(v.x); dst[1] = to_tf32(v.y);
            dst[2] = to_tf32(v.z); dst[3] = to_tf32(v.w);
        }
        __syncthreads();

        float acc[2][4][4] = {};

        #pragma unroll 4
        for (int ks = 0; ks < 16; ks++) {
            const int k0 = ks * 8;
            unsigned int bfr[4][2];
            #pragma unroll
            for (int ni = 0; ni < 4; ni++) {
                int col = wn * 32 + ni * 8 + gp;
                bfr[ni][0] = Bs[(k0 + tq)     * BS_STRIDE + col];
                bfr[ni][1] = Bs[(k0 + tq + 4) * BS_STRIDE + col];
            }
            #pragma unroll
            for (int mi = 0; mi < 2; mi++) {
                int row = wm * 32 + mi * 16 + gp;
                unsigned int a0 = As[row       * AS_STRIDE + k0 + tq];
                unsigned int a1 = As[(row + 8) * AS_STRIDE + k0 + tq];
                unsigned int a2 = As[row       * AS_STRIDE + k0 + tq + 4];
                unsigned int a3 = As[(row + 8) * AS_STRIDE + k0 + tq + 4];
                #pragma unroll
                for (int ni = 0; ni < 4; ni++) {
                    asm volatile(
                        "mma.sync.aligned.m16n8k8.row.col.f32.tf32.tf32.f32 "
                        "{%0,%1,%2,%3}, {%4,%5,%6,%7}, {%8,%9}, {%0,%1,%2,%3};"
                        : "+f"(acc[mi][ni][0]), "+f"(acc[mi][ni][1]),
                          "+f"(acc[mi][ni][2]), "+f"(acc[mi][ni][3])
                        : "r"(a0), "r"(a1), "r"(a2), "r"(a3),
                          "r"(bfr[ni][0]), "r"(bfr[ni][1]));
                }
            }
        }

        #pragma unroll
        for (int ni = 0; ni < 4; ni++) {
            int bcol = n0 + wn * 32 + ni * 8 + 2 * tq;
            float bv0 = g_bias[bcol];
            float bv1 = g_bias[bcol + 1];
            #pragma unroll
            for (int mi = 0; mi < 2; mi++) {
                int row = m0 + wm * 32 + mi * 16 + gp;
                float2 o0 = make_float2(acc[mi][ni][0] + bv0, acc[mi][ni][1] + bv1);
                float2 o1 = make_float2(acc[mi][ni][2] + bv0, acc[mi][ni][3] + bv1);
                *reinterpret_cast<float2*>(&g_preact[(size_t)row * GG + bcol]) = o0;
                *reinterpret_cast<float2*>(&g_preact[(size_t)(row + 8) * GG + bcol]) = o1;
            }
        }
    }
}

// ---------------------------------------------------------------------------
// Kernel 2: recurrent LSTM via TF32 mma.sync. 8 batch rows per CTA (32 CTAs).
// Per step: [8,64] @ Wh[64,256] as m16n8k8 tiles (rows 8..15 = constant 0).
// Warp w owns cols 8w..8w+7 of ALL 4 gate blocks (n-tiles w, w+8, w+16, w+24)
// -> each thread holds f/if/ic/o for its (row, col) pairs IN-THREAD: no
// shuffles, no gate SMEM. c in registers. h double-buffered in SMEM as tf32
// (producer converts once). Wh B-fragments loop-invariant in registers.
// One __syncthreads per step; preact seeds the MMA accumulator (bias incl.);
// 2-step-ahead preact prefetch via 2-unrolled loop (compile-time parity).
// ---------------------------------------------------------------------------
#define LROWS  8
#define HS_PAD 68    // row stride (words): gp*68 mod 32 = 4*gp -> conflict-free

__global__ __launch_bounds__(256, 1) void lstm_mma() {
    const int b0   = blockIdx.x * LROWS;
    const int tid  = threadIdx.x;
    const int warp = tid >> 5;     // 0..7, owns cols 8*warp .. 8*warp+7
    const int lane = tid & 31;
    const int gp   = lane >> 2;    // 0..7  (row within tile / fragment group)
    const int tq   = lane & 3;     // 0..3

    __shared__ unsigned int hs[2][LROWS][HS_PAD];   // h as tf32 bits

    // zero both h buffers (h(-1) = 0; buffer 1 fully rewritten at t=0)
    for (int i = tid; i < 2 * LROWS * HS_PAD; i += 256)
        (&hs[0][0][0])[i] = 0;

    // Wh B-fragments (loop-invariant): q = gate block, kt = k-tile
    unsigned int bfr[4][8][2];
    #pragma unroll
    for (int q = 0; q < 4; q++) {
        const int n0 = q * 64 + 8 * warp;
        #pragma unroll
        for (int kt = 0; kt < 8; kt++) {
            bfr[q][kt][0] = to_tf32(g_Wh[(8 * kt + tq)     * GG + n0 + gp]);
            bfr[q][kt][1] = to_tf32(g_Wh[(8 * kt + tq + 4) * GG + n0 + gp]);
        }
    }

    float c0 = 0.f, c1 = 0.f;   // cell state for (row gp, cols 8w+2tq, +1)
    __syncthreads();

    const int row = b0 + gp;
    // preact pointers (float2), one per gate block; advance GG floats per step
    const float2* pa[4];
    #pragma unroll
    for (int q = 0; q < 4; q++)
        pa[q] = reinterpret_cast<const float2*>(
            g_preact + (size_t)row * TT * GG + q * 64 + 8 * warp + 2 * tq);

    float2 pAv[4], pBv[4];
    #pragma unroll
    for (int q = 0; q < 4; q++) {
        pAv[q] = __ldg(pa[q]);                    // t = 0
        pBv[q] = __ldg(pa[q] + (GG / 2));         // t = 1
    }

    float* hout = g_H + (size_t)row * TT * HH + 8 * warp + 2 * tq;

#define LSTM_STEP(T, RP, WP, PV)                                              \
    {                                                                         \
        float acc[4][4];                                                      \
        _Pragma("unroll")                                                     \
        for (int q = 0; q < 4; q++) {                                         \
            acc[q][0] = PV[q].x; acc[q][1] = PV[q].y;                         \
            acc[q][2] = 0.f;     acc[q][3] = 0.f;                             \
        }                                                                     \
        _Pragma("unroll")                                                     \
        for (int kt = 0; kt < 8; kt++) {                                      \
            unsigned int a0 = hs[RP][gp][8 * kt + tq];                        \
            unsigned int a2 = hs[RP][gp][8 * kt + tq + 4];                    \
            _Pragma("unroll")                                                 \
            for (int q = 0; q < 4; q++) {                                     \
                asm volatile(                                                 \
                    "mma.sync.aligned.m16n8k8.row.col.f32.tf32.tf32.f32 "     \
                    "{%0,%1,%2,%3}, {%4,%5,%6,%7}, {%8,%9}, {%0,%1,%2,%3};"   \
                    : "+f"(acc[q][0]), "+f"(acc[q][1]),                       \
                      "+f"(acc[q][2]), "+f"(acc[q][3])                        \
                    : "r"(a0), "r"(0u), "r"(a2), "r"(0u),                     \
                      "r"(bfr[q][kt][0]), "r"(bfr[q][kt][1]));                \
            }                                                                 \
        }                                                                     \
        if ((T) + 2 < TT) {                                                   \
            _Pragma("unroll")                                                 \
            for (int q = 0; q < 4; q++)                                       \
                PV[q] = __ldg(pa[q] + (size_t)((T) + 2) * (GG / 2));          \
        }                                                                     \
        float fv0 = sig05(acc[0][0]),    fv1 = sig05(acc[0][1]);              \
        float af0 = sig05(acc[1][0]),    af1 = sig05(acc[1][1]);              \
        float ic0 = tanh_fast(acc[2][0]), ic1 = tanh_fast(acc[2][1]);         \
        float ov0 = sig05(acc[3][0]),    ov1 = sig05(acc[3][1]);              \
        c0 = fmaf(c0, fv0, ic0 * af0);                                        \
        c1 = fmaf(c1, fv1, ic1 * af1);                                        \
        float h0 = tanh_fast(c0) * ov0;                                       \
        float h1 = tanh_fast(c1) * ov1;                                       \
        hs[WP][gp][8 * warp + 2 * tq]     = to_tf32(h0);                      \
        hs[WP][gp][8 * warp + 2 * tq + 1] = to_tf32(h1);                      \
        *reinterpret_cast<float2*>(hout + (size_t)(T) * HH) =                 \
            make_float2(h0, h1);                                              \
        __syncthreads();                                                      \
    }

    for (int t = 0; t < TT; t += 2) {
        LSTM_STEP(t,     0, 1, pAv);
        LSTM_STEP(t + 1, 1, 0, pBv);
    }
#undef LSTM_STEP
}

// ---------------------------------------------------------------------------
// Kernel 3: out[m, :] = softmax(h[m, :] @ W_out + b_out)  via TF32 mma
// ---------------------------------------------------------------------------
#define HS_STRIDE 68
#define WS_STRIDE 136

__global__ __launch_bounds__(256, 2) void out_proj(const float* __restrict__ Wout,
                                                   const float* __restrict__ bout,
                                                   float* __restrict__ out) {
    extern __shared__ unsigned int sm[];
    unsigned int* Hs = sm;                                 // 128 * 68 words
    unsigned int* Ws = sm + 128 * HS_STRIDE;               // 64 * 136 words
    float* bs = (float*)(sm + 128 * HS_STRIDE + 64 * WS_STRIDE);  // 128 floats

    const int r0   = blockIdx.x * 128;
    const int tid  = threadIdx.x;
    const int lane = tid & 31;
    const int warp = tid >> 5;
    const int gp = lane >> 2;      // 0..7
    const int tq = lane & 3;       // 0..3

    #pragma unroll
    for (int i = 0; i < 8; i++) {
        int t  = tid + i * 256;        // 0..2047
        int r  = t >> 4;
        int c4 = (t & 15) * 4;
        float4 v = *reinterpret_cast<const float4*>(&g_H[(size_t)(r0 + r) * HH + c4]);
        unsigned int* d = &Hs[r * HS_STRIDE + c4];
        d[0] = to_tf32(v.x); d[1] = to_tf32(v.y);
        d[2] = to_tf32(v.z); d[3] = to_tf32(v.w);
    }
    #pragma unroll
    for (int i = 0; i < 8; i++) {
        int t  = tid + i * 256;
        int k  = t >> 5;
        int c4 = (t & 31) * 4;
        float4 v = *reinterpret_cast<const float4*>(&Wout[k * VV + c4]);
        unsigned int* d = &Ws[k * WS_STRIDE + c4];
        d[0] = to_tf32(v.x); d[1] = to_tf32(v.y);
        d[2] = to_tf32(v.z); d[3] = to_tf32(v.w);
    }
    if (tid < VV) bs[tid] = bout[tid];
    __syncthreads();

    float acc[16][4] = {};
    const int rowA = warp * 16 + gp;

    #pragma unroll
    for (int ks = 0; ks < 8; ks++) {
        const int k0 = ks * 8;
        unsigned int a0 = Hs[rowA       * HS_STRIDE + k0 + tq];
        unsigned int a1 = Hs[(rowA + 8) * HS_STRIDE + k0 + tq];
        unsigned int a2 = Hs[rowA       * HS_STRIDE + k0 + tq + 4];
        unsigned int a3 = Hs[(rowA + 8) * HS_STRIDE + k0 + tq + 4];
        #pragma unroll
        for (int ni = 0; ni < 16; ni++) {
            unsigned int b0 = Ws[(k0 + tq)     * WS_STRIDE + ni * 8 + gp];
            unsigned int b1 = Ws[(k0 + tq + 4) * WS_STRIDE + ni * 8 + gp];
            asm volatile(
                "mma.sync.aligned.m16n8k8.row.col.f32.tf32.tf32.f32 "
                "{%0,%1,%2,%3}, {%4,%5,%6,%7}, {%8,%9}, {%0,%1,%2,%3};"
                : "+f"(acc[ni][0]), "+f"(acc[ni][1]),
                  "+f"(acc[ni][2]), "+f"(acc[ni][3])
                : "r"(a0), "r"(a1), "r"(a2), "r"(a3), "r"(b0), "r"(b1));
        }
    }

    #pragma unroll
    for (int rr = 0; rr < 2; rr++) {
        float l[32];
        #pragma unroll
        for (int ni = 0; ni < 16; ni++) {
            float b0 = bs[ni * 8 + 2 * tq];
            float b1 = bs[ni * 8 + 2 * tq + 1];
            l[2 * ni]     = acc[ni][2 * rr]     + b0;
            l[2 * ni + 1] = acc[ni][2 * rr + 1] + b1;
        }
        float mx = l[0];
        #pragma unroll
        for (int i = 1; i < 32; i++) mx = fmaxf(mx, l[i]);
        mx = fmaxf(mx, __shfl_xor_sync(0xFFFFFFFFu, mx, 1));
        mx = fmaxf(mx, __shfl_xor_sync(0xFFFFFFFFu, mx, 2));

        float s = 0.f;
        #pragma unroll
        for (int i = 0; i < 32; i++) { l[i] = __expf(l[i] - mx); s += l[i]; }
        s += __shfl_xor_sync(0xFFFFFFFFu, s, 1);
        s += __shfl_xor_sync(0xFFFFFFFFu, s, 2);
        float inv = __fdividef(1.f, s);

        size_t row = (size_t)(r0 + rowA + rr * 8);
        #pragma unroll
        for (int ni = 0; ni < 16; ni++) {
            float2 o = make_float2(l[2 * ni] * inv, l[2 * ni + 1] * inv);
            *reinterpret_cast<float2*>(&out[row * VV + ni * 8 + 2 * tq]) = o;
        }
    }
}

// ---------------------------------------------------------------------------
// Launch
// ---------------------------------------------------------------------------
extern "C" void kernel_launch(void* const* d_in, const int* in_sizes, int n_in,
                              void* d_out, int out_size) {
    const float* x    = (const float*)d_in[0];
    const float* Wf   = (const float*)d_in[1];
    const float* bf   = (const float*)d_in[2];
    const float* Wif  = (const float*)d_in[3];
    const float* bif  = (const float*)d_in[4];
    const float* Wic  = (const float*)d_in[5];
    const float* bic  = (const float*)d_in[6];
    const float* Wo   = (const float*)d_in[7];
    const float* bo   = (const float*)d_in[8];
    const float* Wout = (const float*)d_in[9];
    const float* bout = (const float*)d_in[10];
    float* out = (float*)d_out;

    const int gemm_smem = (128 * AS_STRIDE + 128 * BS_STRIDE) * 4;         // 104448 B
    const int proj_smem = (128 * HS_STRIDE + 64 * WS_STRIDE + 128) * 4;    // 70144 B
    cudaFuncSetAttribute(gemm_x, cudaFuncAttributeMaxDynamicSharedMemorySize,
                         gemm_smem);
    cudaFuncSetAttribute(out_proj, cudaFuncAttributeMaxDynamicSharedMemorySize,
                         proj_smem);

    pack_weights<<<1, 256>>>(Wf, bf, Wif, bif, Wic, bic, Wo, bo);
    gemm_x<<<MM / 128, 256, gemm_smem>>>(x);
    lstm_mma<<<BB / LROWS, 256>>>();
    out_proj<<<MM / 128, 256, proj_smem>>>(Wout, bout, out);
}

// round 10
// speedup vs baseline: 1.4144x; 1.4144x over previous
#include <cuda_runtime.h>
#include <cuda_bf16.h>
#include <math.h>

// Problem constants
#define BB   256                 // batch
#define TT   2048                // seq len
#define VV   128                 // vocab / input size
#define HH   64                  // hidden
#define GG   256                 // 4 gates * HH
#define MM   (BB * TT)           // 524288 rows

// Scratch (device-global; no runtime allocation allowed).
// g_preact padded by 2 steps: the lstm prefetch pointer reads up to 2 steps
// past the last row without branching.
__device__ float g_Wx[VV * GG];            // fused x-part weights [128,256]
__device__ float g_Wh[HH * GG];            // fused h-part weights [64,256]
__device__ float g_bias[GG];               // fused gate biases
__device__ float g_preact[(size_t)MM * GG + 2 * GG];  // 512 MB + pad
__device__ float g_H[(size_t)MM * HH];     // 128 MB: hidden states per step

__device__ __forceinline__ unsigned int to_tf32(float v) {
    unsigned int r;
    asm("cvt.rna.tf32.f32 %0, %1;" : "=r"(r) : "f"(v));
    return r;
}
__device__ __forceinline__ float tanh_fast(float x) {
    float y;
    asm("tanh.approx.f32 %0, %1;" : "=f"(y) : "f"(x));
    return y;
}
__device__ __forceinline__ unsigned long long pack2(float lo, float hi) {
    unsigned long long r;
    asm("mov.b64 %0, {%1, %2};" : "=l"(r) : "f"(lo), "f"(hi));
    return r;
}
__device__ __forceinline__ void fma2(unsigned long long& acc,
                                     unsigned long long a, unsigned long long b) {
    asm("fma.rn.f32x2 %0, %1, %2, %0;" : "+l"(acc) : "l"(a), "l"(b));
}
__device__ __forceinline__ float sum2(unsigned long long v) {
    float lo, hi;
    asm("mov.b64 {%0, %1}, %2;" : "=f"(lo), "=f"(hi) : "l"(v));
    return lo + hi;
}

// ---------------------------------------------------------------------------
// Kernel 0: pack 4 gate weight matrices into fused layouts.
// Gate order: 0..63 = f, 64..127 = if, 128..191 = ic(tanh), 192..255 = o
// ---------------------------------------------------------------------------
__global__ void pack_weights(const float* __restrict__ Wf,  const float* __restrict__ bf,
                             const float* __restrict__ Wif, const float* __restrict__ bif,
                             const float* __restrict__ Wic, const float* __restrict__ bic,
                             const float* __restrict__ Wo,  const float* __restrict__ bo) {
    int g = blockIdx.x * blockDim.x + threadIdx.x;
    if (g >= GG) return;
    int gate = g >> 6;
    int col  = g & 63;
    const float* W = (gate == 0) ? Wf : (gate == 1) ? Wif : (gate == 2) ? Wic : Wo;
    const float* bv = (gate == 0) ? bf : (gate == 1) ? bif : (gate == 2) ? bic : bo;
    g_bias[g] = bv[col];
    for (int k = 0; k < VV; k++)
        g_Wx[k * GG + g] = W[k * HH + col];
    for (int j = 0; j < HH; j++)
        g_Wh[j * GG + g] = W[(VV + j) * HH + col];
}

// ---------------------------------------------------------------------------
// Kernel 1: preact[m, g] = x[m, :] @ Wx[:, g] + bias[g]   via TF32 mma.sync
// M=524288, N=256, K=128.  BM=128, whole K resident; CTA loops over all 4
// n-blocks of 64 reusing the A tile (x read from DRAM exactly once).
// ---------------------------------------------------------------------------
#define AS_STRIDE 132
#define BS_STRIDE 72

__global__ __launch_bounds__(256) void gemm_x(const float* __restrict__ x) {
    extern __shared__ unsigned int smem[];
    unsigned int* As = smem;                       // 128 * 132 words
    unsigned int* Bs = smem + 128 * AS_STRIDE;     // 128 * 72 words

    const int m0 = blockIdx.x * 128;
    const int tid  = threadIdx.x;
    const int lane = tid & 31;
    const int warp = tid >> 5;
    const int wm = warp >> 1;      // 0..3  (M)
    const int wn = warp & 1;       // 0..1  (N)
    const int gp = lane >> 2;      // 0..7
    const int tq = lane & 3;       // 0..3

    #pragma unroll
    for (int i = 0; i < 16; i++) {
        int t  = tid + i * 256;            // float4 index 0..4095
        int r  = t >> 5;
        int c4 = (t & 31) * 4;
        float4 v = *reinterpret_cast<const float4*>(&x[(size_t)(m0 + r) * VV + c4]);
        unsigned int* dst = &As[r * AS_STRIDE + c4];
        dst[0] = to_tf32(v.x); dst[1] = to_tf32(v.y);
        dst[2] = to_tf32(v.z); dst[3] = to_tf32(v.w);
    }

    for (int nb = 0; nb < 4; nb++) {
        const int n0 = nb * 64;
        __syncthreads();

        #pragma unroll
        for (int i = 0; i < 8; i++) {
            int t  = tid + i * 256;            // float4 index 0..2047
            int k  = t >> 4;
            int c4 = (t & 15) * 4;
            float4 v = *reinterpret_cast<const float4*>(&g_Wx[(size_t)k * GG + n0 + c4]);
            unsigned int* dst = &Bs[k * BS_STRIDE + c4];
            dst[0] = to_tf32(v.x); dst[1] = to_tf32(v.y);
            dst[2] = to_tf32(v.z); dst[3] = to_tf32(v.w);
        }
        __syncthreads();

        float acc[2][4][4] = {};

        #pragma unroll 4
        for (int ks = 0; ks < 16; ks++) {
            const int k0 = ks * 8;
            unsigned int bfr[4][2];
            #pragma unroll
            for (int ni = 0; ni < 4; ni++) {
                int col = wn * 32 + ni * 8 + gp;
                bfr[ni][0] = Bs[(k0 + tq)     * BS_STRIDE + col];
                bfr[ni][1] = Bs[(k0 + tq + 4) * BS_STRIDE + col];
            }
            #pragma unroll
            for (int mi = 0; mi < 2; mi++) {
                int row = wm * 32 + mi * 16 + gp;
                unsigned int a0 = As[row       * AS_STRIDE + k0 + tq];
                unsigned int a1 = As[(row + 8) * AS_STRIDE + k0 + tq];
                unsigned int a2 = As[row       * AS_STRIDE + k0 + tq + 4];
                unsigned int a3 = As[(row + 8) * AS_STRIDE + k0 + tq + 4];
                #pragma unroll
                for (int ni = 0; ni < 4; ni++) {
                    asm volatile(
                        "mma.sync.aligned.m16n8k8.row.col.f32.tf32.tf32.f32 "
                        "{%0,%1,%2,%3}, {%4,%5,%6,%7}, {%8,%9}, {%0,%1,%2,%3};"
                        : "+f"(acc[mi][ni][0]), "+f"(acc[mi][ni][1]),
                          "+f"(acc[mi][ni][2]), "+f"(acc[mi][ni][3])
                        : "r"(a0), "r"(a1), "r"(a2), "r"(a3),
                          "r"(bfr[ni][0]), "r"(bfr[ni][1]));
                }
            }
        }

        #pragma unroll
        for (int ni = 0; ni < 4; ni++) {
            int bcol = n0 + wn * 32 + ni * 8 + 2 * tq;
            float bv0 = g_bias[bcol];
            float bv1 = g_bias[bcol + 1];
            #pragma unroll
            for (int mi = 0; mi < 2; mi++) {
                int row = m0 + wm * 32 + mi * 16 + gp;
                float2 o0 = make_float2(acc[mi][ni][0] + bv0, acc[mi][ni][1] + bv1);
                float2 o1 = make_float2(acc[mi][ni][2] + bv0, acc[mi][ni][3] + bv1);
                *reinterpret_cast<float2*>(&g_preact[(size_t)row * GG + bcol]) = o0;
                *reinterpret_cast<float2*>(&g_preact[(size_t)(row + 8) * GG + bcol]) = o1;
            }
        }
    }
}

// ---------------------------------------------------------------------------
// Kernel 2: recurrent LSTM (R8 structure + 3 micro-opts).
// One CTA per batch row (256 CTAs, occ 2). Thread tid owns gate (tid&3) of
// column (tid>>2); gate exchange via quad SHFL; ONE barrier per step; h
// double-buffered in SMEM; packed fma.rn.f32x2.
// New: (a) 4 f32x2 accumulators (dep chain 64->32 cyc); (b) pointer-increment
// prefetch (no per-step address mul; g_preact padded); (c) one-time phase
// stagger for b>=148: co-resident CTA pairs are (b, b+148) per the classic
// bid%148 LUT -- staggering breaks their lockstep so compute of one overlaps
// the barrier/tanh latency of the other.
// ---------------------------------------------------------------------------
__global__ __launch_bounds__(256, 2) void lstm_kernel() {
    const int b    = blockIdx.x;
    const int tid  = threadIdx.x;
    const int col  = tid >> 2;          // 0..63
    const int gate = tid & 3;           // 0:f 1:if 2:ic(tanh) 3:o
    const int g    = gate * 64 + col;   // fused gate index
    const int lane = tid & 31;
    const int qbase = lane & ~3;        // quad base lane

    __shared__ __align__(16) float h_s[2][HH];

    // This thread's W_h column, packed as 32 f32x2 pairs
    unsigned long long wh2[HH / 2];
    #pragma unroll
    for (int j = 0; j < HH; j += 2)
        wh2[j >> 1] = pack2(g_Wh[j * GG + g], g_Wh[(j + 1) * GG + g]);

    float c = 0.f;
    if (tid < HH) { h_s[0][tid] = 0.f; h_s[1][tid] = 0.f; }
    __syncthreads();

    const float* pa = g_preact + (size_t)b * TT * GG + g;
    float* hout = g_H + (size_t)b * TT * HH + col;

    // sigmoid(v) = 0.5*tanh(0.5v)+0.5 ; tanh gate (gate==2) uses (1,1,0)
    const float pre    = (gate == 2) ? 1.f : 0.5f;
    const float post_m = (gate == 2) ? 1.f : 0.5f;
    const float post_b = (gate == 2) ? 0.f : 0.5f;

    // 2-deep preact prefetch, pointer-increment form
    float f0 = __ldg(pa);
    float f1 = __ldg(pa + GG);
    const float* pf = pa + 2 * (size_t)GG;

    // Phase stagger: ~260-cycle dependent fma2 chain on opaque zero.
    // d starts at tanh(f0)*0 (opaque to the compiler, numerically 0) and
    // stays 0; the guard is never taken. Delays CTAs b>=148 only.
    if (b >= 148) {
        unsigned long long d = pack2(tanh_fast(f0) * 0.0f, 0.0f);
        #pragma unroll
        for (int r = 0; r < 64; r++)
            fma2(d, d, wh2[r & 31]);
        if (sum2(d) != 0.0f) h_s[0][0] = f0;   // never true
    }

    for (int t = 0; t < TT; t++) {
        float p = f0;
        f0 = f1;
        f1 = __ldg(pf);          // 2 steps ahead; padded tail, value unused
        pf += GG;

        // v = preact + h @ Wh[:, g]   (4 f32x2 accumulators, chain depth 8)
        const ulonglong2* h2 = reinterpret_cast<const ulonglong2*>(h_s[t & 1]);
        unsigned long long a0 = pack2(p, 0.f), a1 = pack2(0.f, 0.f);
        unsigned long long a2 = pack2(0.f, 0.f), a3 = pack2(0.f, 0.f);
        #pragma unroll
        for (int jj = 0; jj < HH / 8; jj++) {
            ulonglong2 hv0 = h2[2 * jj];
            ulonglong2 hv1 = h2[2 * jj + 1];
            fma2(a0, hv0.x, wh2[4 * jj + 0]);
            fma2(a1, hv0.y, wh2[4 * jj + 1]);
            fma2(a2, hv1.x, wh2[4 * jj + 2]);
            fma2(a3, hv1.y, wh2[4 * jj + 3]);
        }
        float v = (sum2(a0) + sum2(a1)) + (sum2(a2) + sum2(a3));

        float val = fmaf(tanh_fast(v * pre), post_m, post_b);

        // Quad gather: gate k of this column lives in lane qbase+k
        float fv  = __shfl_sync(0xFFFFFFFFu, val, qbase + 0);
        float af  = __shfl_sync(0xFFFFFFFFu, val, qbase + 1);
        float add = __shfl_sync(0xFFFFFFFFu, val, qbase + 2);
        float ov  = __shfl_sync(0xFFFFFFFFu, val, qbase + 3);

        // Redundant per-quad update (c identical across the 4 lanes)
        c = fmaf(c, fv, add * af);
        float hn = tanh_fast(c) * ov;

        if (gate == 0) {
            h_s[(t + 1) & 1][col] = hn;
            hout[(size_t)t * HH] = hn;
        }
        __syncthreads();
    }
}

// ---------------------------------------------------------------------------
// Kernel 3: out[m, :] = softmax(h[m, :] @ W_out + b_out)  via TF32 mma
// ---------------------------------------------------------------------------
#define HS_STRIDE 68
#define WS_STRIDE 136

__global__ __launch_bounds__(256, 2) void out_proj(const float* __restrict__ Wout,
                                                   const float* __restrict__ bout,
                                                   float* __restrict__ out) {
    extern __shared__ unsigned int sm[];
    unsigned int* Hs = sm;                                 // 128 * 68 words
    unsigned int* Ws = sm + 128 * HS_STRIDE;               // 64 * 136 words
    float* bs = (float*)(sm + 128 * HS_STRIDE + 64 * WS_STRIDE);  // 128 floats

    const int r0   = blockIdx.x * 128;
    const int tid  = threadIdx.x;
    const int lane = tid & 31;
    const int warp = tid >> 5;
    const int gp = lane >> 2;      // 0..7
    const int tq = lane & 3;       // 0..3

    #pragma unroll
    for (int i = 0; i < 8; i++) {
        int t  = tid + i * 256;        // 0..2047
        int r  = t >> 4;
        int c4 = (t & 15) * 4;
        float4 v = *reinterpret_cast<const float4*>(&g_H[(size_t)(r0 + r) * HH + c4]);
        unsigned int* d = &Hs[r * HS_STRIDE + c4];
        d[0] = to_tf32(v.x); d[1] = to_tf32(v.y);
        d[2] = to_tf32(v.z); d[3] = to_tf32(v.w);
    }
    #pragma unroll
    for (int i = 0; i < 8; i++) {
        int t  = tid + i * 256;
        int k  = t >> 5;
        int c4 = (t & 31) * 4;
        float4 v = *reinterpret_cast<const float4*>(&Wout[k * VV + c4]);
        unsigned int* d = &Ws[k * WS_STRIDE + c4];
        d[0] = to_tf32(v.x); d[1] = to_tf32(v.y);
        d[2] = to_tf32(v.z); d[3] = to_tf32(v.w);
    }
    if (tid < VV) bs[tid] = bout[tid];
    __syncthreads();

    float acc[16][4] = {};
    const int rowA = warp * 16 + gp;

    #pragma unroll
    for (int ks = 0; ks < 8; ks++) {
        const int k0 = ks * 8;
        unsigned int a0 = Hs[rowA       * HS_STRIDE + k0 + tq];
        unsigned int a1 = Hs[(rowA + 8) * HS_STRIDE + k0 + tq];
        unsigned int a2 = Hs[rowA       * HS_STRIDE + k0 + tq + 4];
        unsigned int a3 = Hs[(rowA + 8) * HS_STRIDE + k0 + tq + 4];
        #pragma unroll
        for (int ni = 0; ni < 16; ni++) {
            unsigned int b0 = Ws[(k0 + tq)     * WS_STRIDE + ni * 8 + gp];
            unsigned int b1 = Ws[(k0 + tq + 4) * WS_STRIDE + ni * 8 + gp];
            asm volatile(
                "mma.sync.aligned.m16n8k8.row.col.f32.tf32.tf32.f32 "
                "{%0,%1,%2,%3}, {%4,%5,%6,%7}, {%8,%9}, {%0,%1,%2,%3};"
                : "+f"(acc[ni][0]), "+f"(acc[ni][1]),
                  "+f"(acc[ni][2]), "+f"(acc[ni][3])
                : "r"(a0), "r"(a1), "r"(a2), "r"(a3), "r"(b0), "r"(b1));
        }
    }

    #pragma unroll
    for (int rr = 0; rr < 2; rr++) {
        float l[32];
        #pragma unroll
        for (int ni = 0; ni < 16; ni++) {
            float b0 = bs[ni * 8 + 2 * tq];
            float b1 = bs[ni * 8 + 2 * tq + 1];
            l[2 * ni]     = acc[ni][2 * rr]     + b0;
            l[2 * ni + 1] = acc[ni][2 * rr + 1] + b1;
        }
        float mx = l[0];
        #pragma unroll
        for (int i = 1; i < 32; i++) mx = fmaxf(mx, l[i]);
        mx = fmaxf(mx, __shfl_xor_sync(0xFFFFFFFFu, mx, 1));
        mx = fmaxf(mx, __shfl_xor_sync(0xFFFFFFFFu, mx, 2));

        float s = 0.f;
        #pragma unroll
        for (int i = 0; i < 32; i++) { l[i] = __expf(l[i] - mx); s += l[i]; }
        s += __shfl_xor_sync(0xFFFFFFFFu, s, 1);
        s += __shfl_xor_sync(0xFFFFFFFFu, s, 2);
        float inv = __fdividef(1.f, s);

        size_t row = (size_t)(r0 + rowA + rr * 8);
        #pragma unroll
        for (int ni = 0; ni < 16; ni++) {
            float2 o = make_float2(l[2 * ni] * inv, l[2 * ni + 1] * inv);
            *reinterpret_cast<float2*>(&out[row * VV + ni * 8 + 2 * tq]) = o;
        }
    }
}

// ---------------------------------------------------------------------------
// Launch
// ---------------------------------------------------------------------------
extern "C" void kernel_launch(void* const* d_in, const int* in_sizes, int n_in,
                              void* d_out, int out_size) {
    const float* x    = (const float*)d_in[0];
    const float* Wf   = (const float*)d_in[1];
    const float* bf   = (const float*)d_in[2];
    const float* Wif  = (const float*)d_in[3];
    const float* bif  = (const float*)d_in[4];
    const float* Wic  = (const float*)d_in[5];
    const float* bic  = (const float*)d_in[6];
    const float* Wo   = (const float*)d_in[7];
    const float* bo   = (const float*)d_in[8];
    const float* Wout = (const float*)d_in[9];
    const float* bout = (const float*)d_in[10];
    float* out = (float*)d_out;

    const int gemm_smem = (128 * AS_STRIDE + 128 * BS_STRIDE) * 4;         // 104448 B
    const int proj_smem = (128 * HS_STRIDE + 64 * WS_STRIDE + 128) * 4;    // 70144 B
    cudaFuncSetAttribute(gemm_x, cudaFuncAttributeMaxDynamicSharedMemorySize,
                         gemm_smem);
    cudaFuncSetAttribute(out_proj, cudaFuncAttributeMaxDynamicSharedMemorySize,
                         proj_smem);

    pack_weights<<<1, 256>>>(Wf, bf, Wif, bif, Wic, bic, Wo, bo);
    gemm_x<<<MM / 128, 256, gemm_smem>>>(x);
    lstm_kernel<<<BB, 256>>>();
    out_proj<<<MM / 128, 256, proj_smem>>>(Wout, bout, out);
}

// round 11
// speedup vs baseline: 1.5860x; 1.1213x over previous
#include <cuda_runtime.h>
#include <cuda_bf16.h>
#include <math.h>

// Problem constants
#define BB   256                 // batch
#define TT   2048                // seq len
#define VV   128                 // vocab / input size
#define HH   64                  // hidden
#define GG   256                 // 4 gates * HH
#define MM   (BB * TT)           // 524288 rows

// Scratch (device-global; no runtime allocation allowed).
__device__ __nv_bfloat16 g_Wxbf[GG * VV];  // x-part weights, [n][k] bf16
__device__ float g_Wh[HH * GG];            // fused h-part weights [64,256]
__device__ float g_bias[GG];               // fused gate biases
__device__ float g_preact[(size_t)MM * GG + 2 * GG];  // 512 MB + pad
__device__ float g_H[(size_t)MM * HH];     // 128 MB: hidden states per step

__device__ __forceinline__ unsigned int to_tf32(float v) {
    unsigned int r;
    asm("cvt.rna.tf32.f32 %0, %1;" : "=r"(r) : "f"(v));
    return r;
}
__device__ __forceinline__ unsigned int pack_bf2(float hi, float lo) {
    unsigned int r;
    asm("cvt.rn.bf16x2.f32 %0, %1, %2;" : "=r"(r) : "f"(hi), "f"(lo));
    return r;
}
__device__ __forceinline__ float tanh_fast(float x) {
    float y;
    asm("tanh.approx.f32 %0, %1;" : "=f"(y) : "f"(x));
    return y;
}
__device__ __forceinline__ unsigned long long pack2(float lo, float hi) {
    unsigned long long r;
    asm("mov.b64 %0, {%1, %2};" : "=l"(r) : "f"(lo), "f"(hi));
    return r;
}
__device__ __forceinline__ void fma2(unsigned long long& acc,
                                     unsigned long long a, unsigned long long b) {
    asm("fma.rn.f32x2 %0, %1, %2, %0;" : "+l"(acc) : "l"(a), "l"(b));
}
__device__ __forceinline__ float sum2(unsigned long long v) {
    float lo, hi;
    asm("mov.b64 {%0, %1}, %2;" : "=f"(lo), "=f"(hi) : "l"(v));
    return lo + hi;
}

// ---------------------------------------------------------------------------
// Kernel 0: pack gate weights. Grid 192 x 256 threads: block j < 128 packs
// x-row j into bf16 [n][k]; block j >= 128 packs h-row (j-128) fp32 [k][n].
// Gate order: 0..63 = f, 64..127 = if, 128..191 = ic(tanh), 192..255 = o
// ---------------------------------------------------------------------------
__global__ void pack_weights(const float* __restrict__ Wf,  const float* __restrict__ bf,
                             const float* __restrict__ Wif, const float* __restrict__ bif,
                             const float* __restrict__ Wic, const float* __restrict__ bic,
                             const float* __restrict__ Wo,  const float* __restrict__ bo) {
    int g = threadIdx.x;               // 0..255
    int j = blockIdx.x;                // 0..191
    int gate = g >> 6;
    int col  = g & 63;
    const float* W = (gate == 0) ? Wf : (gate == 1) ? Wif : (gate == 2) ? Wic : Wo;
    if (j < VV) {
        g_Wxbf[g * VV + j] = __float2bfloat16(W[j * HH + col]);
    } else {
        int k = j - VV;
        g_Wh[k * GG + g] = W[(VV + k) * HH + col];
    }
    if (j == 0) {
        const float* bv = (gate == 0) ? bf : (gate == 1) ? bif : (gate == 2) ? bic : bo;
        g_bias[g] = bv[col];
    }
}

// ---------------------------------------------------------------------------
// Kernel 1: preact[m, g] = x[m, :] @ Wx[:, g] + bias[g]  via BF16 mma.sync
// m16n8k16 (2x tf32 rate). M=524288, N=256, K=128. BM=128, whole K resident;
// CTA loops the 4 n-blocks of 64 reusing the A tile. 8 warps 4(M) x 2(N),
// warp = 32x32. SMEM bf16, word-stride 68 (conflict-free fragment loads).
// ---------------------------------------------------------------------------
#define AW 68   // A row stride in 32-bit words (136 bf16)
#define BW 68   // B row stride in 32-bit words

__global__ __launch_bounds__(256) void gemm_x(const float* __restrict__ x) {
    extern __shared__ unsigned int smem[];
    unsigned int* As = smem;                 // 128 rows * 68 words (k pairs)
    unsigned int* Bs = smem + 128 * AW;      // 64 n-rows * 68 words (k pairs)

    const int m0 = blockIdx.x * 128;
    const int tid  = threadIdx.x;
    const int lane = tid & 31;
    const int warp = tid >> 5;
    const int wm = warp >> 1;      // 0..3  (M)
    const int wn = warp & 1;       // 0..1  (N)
    const int gp = lane >> 2;      // 0..7
    const int tq = lane & 3;       // 0..3

    // ---- Load A tile: 128 rows x 128 K, fp32 -> bf16 pairs. 16 f4/thread.
    #pragma unroll
    for (int i = 0; i < 16; i++) {
        int t  = tid + i * 256;            // float4 index 0..4095
        int r  = t >> 5;
        int c4 = (t & 31) * 4;             // k offset (multiple of 4)
        float4 v = *reinterpret_cast<const float4*>(&x[(size_t)(m0 + r) * VV + c4]);
        uint2 u;
        u.x = pack_bf2(v.y, v.x);          // lo = k, hi = k+1
        u.y = pack_bf2(v.w, v.z);
        *reinterpret_cast<uint2*>(&As[r * AW + (c4 >> 1)]) = u;
    }

    for (int nb = 0; nb < 4; nb++) {
        const int n0 = nb * 64;
        __syncthreads();   // A ready (first iter) / prev mma done with Bs

        // ---- Load B tile: 64 n-rows x 128 k bf16 from g_Wxbf. 4 f4/thread.
        #pragma unroll
        for (int i = 0; i < 4; i++) {
            int t  = tid + i * 256;        // float4 index 0..1023
            int r  = t >> 4;               // n-row 0..63
            int cc = t & 15;               // float4 within row (8 bf16)
            uint4 v = *reinterpret_cast<const uint4*>(
                &g_Wxbf[(size_t)(n0 + r) * VV + cc * 8]);
            *reinterpret_cast<uint4*>(&Bs[r * BW + cc * 4]) = v;
        }
        __syncthreads();

        float acc[2][4][4] = {};

        #pragma unroll
        for (int ks = 0; ks < 8; ks++) {          // k16 steps
            const int kw = ks * 8;                // word offset within row
            unsigned int bfr[4][2];
            #pragma unroll
            for (int ni = 0; ni < 4; ni++) {
                int n = wn * 32 + ni * 8 + gp;
                bfr[ni][0] = Bs[n * BW + kw + tq];
                bfr[ni][1] = Bs[n * BW + kw + tq + 4];
            }
            #pragma unroll
            for (int mi = 0; mi < 2; mi++) {
                int row = wm * 32 + mi * 16 + gp;
                unsigned int a0 = As[row       * AW + kw + tq];
                unsigned int a1 = As[(row + 8) * AW + kw + tq];
                unsigned int a2 = As[row       * AW + kw + tq + 4];
                unsigned int a3 = As[(row + 8) * AW + kw + tq + 4];
                #pragma unroll
                for (int ni = 0; ni < 4; ni++) {
                    asm volatile(
                        "mma.sync.aligned.m16n8k16.row.col.f32.bf16.bf16.f32 "
                        "{%0,%1,%2,%3}, {%4,%5,%6,%7}, {%8,%9}, {%0,%1,%2,%3};"
                        : "+f"(acc[mi][ni][0]), "+f"(acc[mi][ni][1]),
                          "+f"(acc[mi][ni][2]), "+f"(acc[mi][ni][3])
                        : "r"(a0), "r"(a1), "r"(a2), "r"(a3),
                          "r"(bfr[ni][0]), "r"(bfr[ni][1]));
                }
            }
        }

        // ---- Epilogue: bias + store (float2 per fragment-row)
        #pragma unroll
        for (int ni = 0; ni < 4; ni++) {
            int bcol = n0 + wn * 32 + ni * 8 + 2 * tq;
            float bv0 = g_bias[bcol];
            float bv1 = g_bias[bcol + 1];
            #pragma unroll
            for (int mi = 0; mi < 2; mi++) {
                int row = m0 + wm * 32 + mi * 16 + gp;
                float2 o0 = make_float2(acc[mi][ni][0] + bv0, acc[mi][ni][1] + bv1);
                float2 o1 = make_float2(acc[mi][ni][2] + bv0, acc[mi][ni][3] + bv1);
                *reinterpret_cast<float2*>(&g_preact[(size_t)row * GG + bcol]) = o0;
                *reinterpret_cast<float2*>(&g_preact[(size_t)(row + 8) * GG + bcol]) = o1;
            }
        }
    }
}

// ---------------------------------------------------------------------------
// Kernel 2: recurrent LSTM (unchanged from R10 best).
// One CTA per batch row (256 CTAs, occ 2). Thread tid owns gate (tid&3) of
// column (tid>>2); gate exchange via quad SHFL; ONE barrier per step; h
// double-buffered in SMEM; packed fma.rn.f32x2.
// ---------------------------------------------------------------------------
__global__ __launch_bounds__(256, 2) void lstm_kernel() {
    const int b    = blockIdx.x;
    const int tid  = threadIdx.x;
    const int col  = tid >> 2;          // 0..63
    const int gate = tid & 3;           // 0:f 1:if 2:ic(tanh) 3:o
    const int g    = gate * 64 + col;   // fused gate index
    const int lane = tid & 31;
    const int qbase = lane & ~3;        // quad base lane

    __shared__ __align__(16) float h_s[2][HH];

    unsigned long long wh2[HH / 2];
    #pragma unroll
    for (int j = 0; j < HH; j += 2)
        wh2[j >> 1] = pack2(g_Wh[j * GG + g], g_Wh[(j + 1) * GG + g]);

    float c = 0.f;
    if (tid < HH) { h_s[0][tid] = 0.f; h_s[1][tid] = 0.f; }
    __syncthreads();

    const float* pa = g_preact + (size_t)b * TT * GG + g;
    float* hout = g_H + (size_t)b * TT * HH + col;

    const float pre    = (gate == 2) ? 1.f : 0.5f;
    const float post_m = (gate == 2) ? 1.f : 0.5f;
    const float post_b = (gate == 2) ? 0.f : 0.5f;

    float f0 = __ldg(pa);
    float f1 = __ldg(pa + GG);
    const float* pf = pa + 2 * (size_t)GG;

    if (b >= 148) {
        unsigned long long d = pack2(tanh_fast(f0) * 0.0f, 0.0f);
        #pragma unroll
        for (int r = 0; r < 64; r++)
            fma2(d, d, wh2[r & 31]);
        if (sum2(d) != 0.0f) h_s[0][0] = f0;   // never true
    }

    for (int t = 0; t < TT; t++) {
        float p = f0;
        f0 = f1;
        f1 = __ldg(pf);
        pf += GG;

        const ulonglong2* h2 = reinterpret_cast<const ulonglong2*>(h_s[t & 1]);
        unsigned long long a0 = pack2(p, 0.f), a1 = pack2(0.f, 0.f);
        unsigned long long a2 = pack2(0.f, 0.f), a3 = pack2(0.f, 0.f);
        #pragma unroll
        for (int jj = 0; jj < HH / 8; jj++) {
            ulonglong2 hv0 = h2[2 * jj];
            ulonglong2 hv1 = h2[2 * jj + 1];
            fma2(a0, hv0.x, wh2[4 * jj + 0]);
            fma2(a1, hv0.y, wh2[4 * jj + 1]);
            fma2(a2, hv1.x, wh2[4 * jj + 2]);
            fma2(a3, hv1.y, wh2[4 * jj + 3]);
        }
        float v = (sum2(a0) + sum2(a1)) + (sum2(a2) + sum2(a3));

        float val = fmaf(tanh_fast(v * pre), post_m, post_b);

        float fv  = __shfl_sync(0xFFFFFFFFu, val, qbase + 0);
        float af  = __shfl_sync(0xFFFFFFFFu, val, qbase + 1);
        float add = __shfl_sync(0xFFFFFFFFu, val, qbase + 2);
        float ov  = __shfl_sync(0xFFFFFFFFu, val, qbase + 3);

        c = fmaf(c, fv, add * af);
        float hn = tanh_fast(c) * ov;

        if (gate == 0) {
            h_s[(t + 1) & 1][col] = hn;
            hout[(size_t)t * HH] = hn;
        }
        __syncthreads();
    }
}

// ---------------------------------------------------------------------------
// Kernel 3: out[m, :] = softmax(h[m, :] @ W_out + b_out)  via TF32 mma
// (unchanged from R10 best)
// ---------------------------------------------------------------------------
#define HS_STRIDE 68
#define WS_STRIDE 136

__global__ __launch_bounds__(256, 2) void out_proj(const float* __restrict__ Wout,
                                                   const float* __restrict__ bout,
                                                   float* __restrict__ out) {
    extern __shared__ unsigned int sm[];
    unsigned int* Hs = sm;                                 // 128 * 68 words
    unsigned int* Ws = sm + 128 * HS_STRIDE;               // 64 * 136 words
    float* bs = (float*)(sm + 128 * HS_STRIDE + 64 * WS_STRIDE);  // 128 floats

    const int r0   = blockIdx.x * 128;
    const int tid  = threadIdx.x;
    const int lane = tid & 31;
    const int warp = tid >> 5;
    const int gp = lane >> 2;      // 0..7
    const int tq = lane & 3;       // 0..3

    #pragma unroll
    for (int i = 0; i < 8; i++) {
        int t  = tid + i * 256;        // 0..2047
        int r  = t >> 4;
        int c4 = (t & 15) * 4;
        float4 v = *reinterpret_cast<const float4*>(&g_H[(size_t)(r0 + r) * HH + c4]);
        unsigned int* d = &Hs[r * HS_STRIDE + c4];
        d[0] = to_tf32(v.x); d[1] = to_tf32(v.y);
        d[2] = to_tf32(v.z); d[3] = to_tf32(v.w);
    }
    #pragma unroll
    for (int i = 0; i < 8; i++) {
        int t  = tid + i * 256;
        int k  = t >> 5;
        int c4 = (t & 31) * 4;
        float4 v = *reinterpret_cast<const float4*>(&Wout[k * VV + c4]);
        unsigned int* d = &Ws[k * WS_STRIDE + c4];
        d[0] = to_tf32(v.x); d[1] = to_tf32(v.y);
        d[2] = to_tf32(v.z); d[3] = to_tf32(v.w);
    }
    if (tid < VV) bs[tid] = bout[tid];
    __syncthreads();

    float acc[16][4] = {};
    const int rowA = warp * 16 + gp;

    #pragma unroll
    for (int ks = 0; ks < 8; ks++) {
        const int k0 = ks * 8;
        unsigned int a0 = Hs[rowA       * HS_STRIDE + k0 + tq];
        unsigned int a1 = Hs[(rowA + 8) * HS_STRIDE + k0 + tq];
        unsigned int a2 = Hs[rowA       * HS_STRIDE + k0 + tq + 4];
        unsigned int a3 = Hs[(rowA + 8) * HS_STRIDE + k0 + tq + 4];
        #pragma unroll
        for (int ni = 0; ni < 16; ni++) {
            unsigned int b0 = Ws[(k0 + tq)     * WS_STRIDE + ni * 8 + gp];
            unsigned int b1 = Ws[(k0 + tq + 4) * WS_STRIDE + ni * 8 + gp];
            asm volatile(
                "mma.sync.aligned.m16n8k8.row.col.f32.tf32.tf32.f32 "
                "{%0,%1,%2,%3}, {%4,%5,%6,%7}, {%8,%9}, {%0,%1,%2,%3};"
                : "+f"(acc[ni][0]), "+f"(acc[ni][1]),
                  "+f"(acc[ni][2]), "+f"(acc[ni][3])
                : "r"(a0), "r"(a1), "r"(a2), "r"(a3), "r"(b0), "r"(b1));
        }
    }

    #pragma unroll
    for (int rr = 0; rr < 2; rr++) {
        float l[32];
        #pragma unroll
        for (int ni = 0; ni < 16; ni++) {
            float b0 = bs[ni * 8 + 2 * tq];
            float b1 = bs[ni * 8 + 2 * tq + 1];
            l[2 * ni]     = acc[ni][2 * rr]     + b0;
            l[2 * ni + 1] = acc[ni][2 * rr + 1] + b1;
        }
        float mx = l[0];
        #pragma unroll
        for (int i = 1; i < 32; i++) mx = fmaxf(mx, l[i]);
        mx = fmaxf(mx, __shfl_xor_sync(0xFFFFFFFFu, mx, 1));
        mx = fmaxf(mx, __shfl_xor_sync(0xFFFFFFFFu, mx, 2));

        float s = 0.f;
        #pragma unroll
        for (int i = 0; i < 32; i++) { l[i] = __expf(l[i] - mx); s += l[i]; }
        s += __shfl_xor_sync(0xFFFFFFFFu, s, 1);
        s += __shfl_xor_sync(0xFFFFFFFFu, s, 2);
        float inv = __fdividef(1.f, s);

        size_t row = (size_t)(r0 + rowA + rr * 8);
        #pragma unroll
        for (int ni = 0; ni < 16; ni++) {
            float2 o = make_float2(l[2 * ni] * inv, l[2 * ni + 1] * inv);
            *reinterpret_cast<float2*>(&out[row * VV + ni * 8 + 2 * tq]) = o;
        }
    }
}

// ---------------------------------------------------------------------------
// Launch
// ---------------------------------------------------------------------------
extern "C" void kernel_launch(void* const* d_in, const int* in_sizes, int n_in,
                              void* d_out, int out_size) {
    const float* x    = (const float*)d_in[0];
    const float* Wf   = (const float*)d_in[1];
    const float* bf   = (const float*)d_in[2];
    const float* Wif  = (const float*)d_in[3];
    const float* bif  = (const float*)d_in[4];
    const float* Wic  = (const float*)d_in[5];
    const float* bic  = (const float*)d_in[6];
    const float* Wo   = (const float*)d_in[7];
    const float* bo   = (const float*)d_in[8];
    const float* Wout = (const float*)d_in[9];
    const float* bout = (const float*)d_in[10];
    float* out = (float*)d_out;

    const int gemm_smem = (128 * AW + 64 * BW) * 4;                        // 52224 B
    const int proj_smem = (128 * HS_STRIDE + 64 * WS_STRIDE + 128) * 4;    // 70144 B
    cudaFuncSetAttribute(gemm_x, cudaFuncAttributeMaxDynamicSharedMemorySize,
                         gemm_smem);
    cudaFuncSetAttribute(out_proj, cudaFuncAttributeMaxDynamicSharedMemorySize,
                         proj_smem);

    pack_weights<<<192, 256>>>(Wf, bf, Wif, bif, Wic, bic, Wo, bo);
    gemm_x<<<MM / 128, 256, gemm_smem>>>(x);
    lstm_kernel<<<BB, 256>>>();
    out_proj<<<MM / 128, 256, proj_smem>>>(Wout, bout, out);
}